// round 15
// baseline (speedup 1.0000x reference)
#include <cuda_runtime.h>
#include <stdint.h>
#include <math.h>

#define Bn 4
#define Sn 2048
#define Dn 1024
#define Hn 16
#define HDn 64
#define Mn 8192          // B*S

// ---- scratch (allocation-free rule: __device__ globals) ----
// intermediates consumed only by GEMMs/attention are stored as tf32 bit patterns
__device__ uint32_t g_ln1[(size_t)Mn * Dn];      // tf32 bits
__device__ uint32_t g_qkv[(size_t)Mn * 3 * Dn];  // tf32 bits
__device__ uint32_t g_att[(size_t)Mn * Dn];      // tf32 bits
__device__ float    g_x1 [(size_t)Mn * Dn];      // fp32 (residual + LN2 input)
__device__ uint32_t g_ln2[(size_t)Mn * Dn];      // tf32 bits
__device__ uint32_t g_fc [(size_t)Mn * 4 * Dn];  // tf32 bits
__device__ uint32_t g_wt[12582912];              // 48 MB: tf32 weights [K,N]
#define WT_QKV 0
#define WT_AO  3145728
#define WT_FC  4194304
#define WT_OUT 8388608

// ---------------- helpers ----------------
__device__ __forceinline__ float gelu_exact(float v) {
    return 0.5f * v * (1.0f + erff(v * 0.7071067811865476f));
}
__device__ __forceinline__ uint32_t f2tf(float f) {
    uint32_t u;
    asm("cvt.rna.tf32.f32 %0, %1;" : "=r"(u) : "f"(f));
    return u;
}
__device__ __forceinline__ void mma_tf32(float* d, const uint32_t* a,
                                         uint32_t b0, uint32_t b1) {
    asm volatile(
        "mma.sync.aligned.m16n8k8.row.col.f32.tf32.tf32.f32 "
        "{%0,%1,%2,%3}, {%4,%5,%6,%7}, {%8,%9}, {%0,%1,%2,%3};\n"
        : "+f"(d[0]), "+f"(d[1]), "+f"(d[2]), "+f"(d[3])
        : "r"(a[0]), "r"(a[1]), "r"(a[2]), "r"(a[3]), "r"(b0), "r"(b1));
}
__device__ __forceinline__ uint32_t smem_u32(const void* p) {
    uint32_t a;
    asm("{ .reg .u64 t; cvta.to.shared.u64 t, %1; cvt.u32.u64 %0, t; }"
        : "=r"(a) : "l"(p));
    return a;
}
__device__ __forceinline__ void cp_async16(uint32_t dst, const void* src) {
    asm volatile("cp.async.ca.shared.global [%0], [%1], 16;"
                 :: "r"(dst), "l"(src) : "memory");
}
#define CP_COMMIT() asm volatile("cp.async.commit_group;" ::: "memory")
#define CP_WAIT0()  asm volatile("cp.async.wait_group 0;" ::: "memory")
#define CP_WAIT1()  asm volatile("cp.async.wait_group 1;" ::: "memory")

// ---------------- LayerNorm: fp32 in -> tf32 bits out ----------------
__global__ void __launch_bounds__(256) ln_kernel(const float* __restrict__ x,
                                                 const float* __restrict__ g,
                                                 const float* __restrict__ bta,
                                                 uint32_t* __restrict__ out)
{
    int row = blockIdx.x;
    const float* xr = x + (size_t)row * Dn;
    uint32_t* orow = out + (size_t)row * Dn;
    float s = 0.f, s2 = 0.f;
    for (int i = threadIdx.x; i < Dn; i += 256) {
        float v = xr[i];
        s += v;
        s2 = fmaf(v, v, s2);
    }
    #pragma unroll
    for (int off = 16; off; off >>= 1) {
        s  += __shfl_xor_sync(0xffffffffu, s,  off);
        s2 += __shfl_xor_sync(0xffffffffu, s2, off);
    }
    __shared__ float rs[8], rs2[8];
    int w = threadIdx.x >> 5, lane = threadIdx.x & 31;
    if (lane == 0) { rs[w] = s; rs2[w] = s2; }
    __syncthreads();
    if (threadIdx.x < 32) {
        s  = (lane < 8) ? rs[lane]  : 0.f;
        s2 = (lane < 8) ? rs2[lane] : 0.f;
        #pragma unroll
        for (int off = 4; off; off >>= 1) {
            s  += __shfl_xor_sync(0xffffffffu, s,  off);
            s2 += __shfl_xor_sync(0xffffffffu, s2, off);
        }
        if (lane == 0) { rs[0] = s; rs2[0] = s2; }
    }
    __syncthreads();
    float mu  = rs[0] * (1.f / Dn);
    float var = rs2[0] * (1.f / Dn) - mu * mu;
    float inv = rsqrtf(var + 1e-5f);
    for (int i = threadIdx.x; i < Dn; i += 256) {
        orow[i] = f2tf((xr[i] - mu) * inv * g[i] + bta[i]);
    }
}

// ---------------- weight prep: elementwise fp32 -> tf32 bits ----------------
__global__ void __launch_bounds__(256) wconv(const float* __restrict__ W,
                                             uint32_t* __restrict__ Wt)
{
    int i = (blockIdx.x * 256 + threadIdx.x) * 4;
    float4 v = *(const float4*)(W + i);
    uint4 u;
    u.x = f2tf(v.x); u.y = f2tf(v.y); u.z = f2tf(v.z); u.w = f2tf(v.w);
    *(uint4*)(Wt + i) = u;
}

// =====================================================================
// TF32 tensor-core GEMM (unchanged from R14)
// =====================================================================
#define SPAC 264  // words per (k8,c4) A-chunk: 8 m16-blocks * 32 + 8 pad
#define SPB 264   // B smem row stride (256 + 8)
#define ASZ (8 * SPAC)
#define BSZ (16 * SPB)
#define GEMM_SMEM ((2 * ASZ + 2 * BSZ) * 4)

template<int EPI, int OTF>
__global__ void __launch_bounds__(256) gemm_tf32(
    const uint32_t* __restrict__ A, const uint32_t* __restrict__ Bt,
    const float* __restrict__ bias, const float* __restrict__ res,
    void* __restrict__ Cv, int M, int N, int K)
{
    extern __shared__ uint32_t smem[];
    uint32_t sb = smem_u32(smem);
    uint32_t* As = smem;              // [2][8 chunks][SPAC]
    uint32_t* Bs = smem + 2 * ASZ;    // [2][16][SPB]
    const uint32_t B0BYTE = 2 * ASZ * 4;

    int tid = threadIdx.x;
    int lane = tid & 31, wid = tid >> 5;
    int warp_m = wid >> 2;            // 0..1
    int warp_n = wid & 3;             // 0..3
    int r = lane >> 2, c = lane & 3;

    int rowBase = blockIdx.y * 128;
    int colBase = blockIdx.x * 256;

    int arow = tid >> 1;
    int ak8  = tid & 1;
    const uint32_t* Ap = A + (size_t)(rowBase + arow) * K + ak8 * 8;
    int abase = ak8 * 4 * SPAC + (arow >> 4) * 32 + (arow & 7) * 4 + ((arow >> 3) & 1) * 2;

    int bk0 = tid >> 6;               // 0..3
    int bn4 = tid & 63;               // 0..63
    const uint32_t* Bp = Bt + (size_t)bk0 * N + colBase + bn4 * 4;

    float acc[4][8][4];
    #pragma unroll
    for (int mi = 0; mi < 4; mi++)
        #pragma unroll
        for (int ni = 0; ni < 8; ni++)
            #pragma unroll
            for (int e = 0; e < 4; e++) acc[mi][ni][e] = 0.f;

    {
        uint32_t bdst = sb + B0BYTE;
        #pragma unroll
        for (int j = 0; j < 4; j++)
            cp_async16(bdst + (uint32_t)(((bk0 + 4 * j) * SPB + bn4 * 4) * 4),
                       Bp + (size_t)(4 * j) * N);
        CP_COMMIT();
        uint4 apf[2];
        #pragma unroll
        for (int j = 0; j < 2; j++)
            apf[j] = *(const uint4*)(Ap + j * 4);
        #pragma unroll
        for (int j = 0; j < 2; j++) {
            uint32_t* a = &As[abase + j];
            a[0 * SPAC] = apf[j].x; a[1 * SPAC] = apf[j].y;
            a[2 * SPAC] = apf[j].z; a[3 * SPAC] = apf[j].w;
        }
        CP_WAIT0();
    }
    __syncthreads();

    int nk = K >> 4;
    int buf = 0;
    uint4 apf[2];
    for (int kb = 0; kb < nk; kb++) {
        if (kb + 1 < nk) {
            int nb = buf ^ 1;
            uint32_t bdst = sb + B0BYTE + (uint32_t)(nb * BSZ * 4);
            const uint32_t* Bsrc = Bp + (size_t)((kb + 1) * 16) * N;
            #pragma unroll
            for (int j = 0; j < 4; j++)
                cp_async16(bdst + (uint32_t)(((bk0 + 4 * j) * SPB + bn4 * 4) * 4),
                           Bsrc + (size_t)(4 * j) * N);
            CP_COMMIT();
            const uint32_t* Apn = Ap + (kb + 1) * 16;
            #pragma unroll
            for (int j = 0; j < 2; j++)
                apf[j] = *(const uint4*)(Apn + j * 4);
        }

        const uint32_t* Ab = As + buf * ASZ;
        const uint32_t* Bb = Bs + buf * BSZ;
        #pragma unroll
        for (int ks = 0; ks < 2; ks++) {
            int kk = ks * 8;
            uint32_t af[4][4];
            const uint32_t* Ac = Ab + (ks * 4 + c) * SPAC + r * 4;
            #pragma unroll
            for (int mi = 0; mi < 4; mi++) {
                uint4 va = *(const uint4*)(Ac + (warp_m * 4 + mi) * 32);
                af[mi][0] = va.x;
                af[mi][1] = va.z;
                af[mi][2] = va.y;
                af[mi][3] = va.w;
            }
            uint32_t bf[8][2];
            #pragma unroll
            for (int ni = 0; ni < 8; ni++) {
                int n0 = warp_n * 64 + ni * 8 + r;
                bf[ni][0] = Bb[(kk + c) * SPB + n0];
                bf[ni][1] = Bb[(kk + c + 4) * SPB + n0];
            }
            #pragma unroll
            for (int mi = 0; mi < 4; mi++)
                #pragma unroll
                for (int ni = 0; ni < 8; ni++)
                    mma_tf32(acc[mi][ni], af[mi], bf[ni][0], bf[ni][1]);
        }

        if (kb + 1 < nk) {
            int nb = buf ^ 1;
            uint32_t* An = As + nb * ASZ;
            #pragma unroll
            for (int j = 0; j < 2; j++) {
                uint32_t* a = &An[abase + j];
                a[0 * SPAC] = apf[j].x; a[1 * SPAC] = apf[j].y;
                a[2 * SPAC] = apf[j].z; a[3 * SPAC] = apf[j].w;
            }
            CP_WAIT0();
            __syncthreads();
            buf = nb;
        }
    }

    float*    Cf = (float*)Cv;
    uint32_t* Cu = (uint32_t*)Cv;
    #pragma unroll
    for (int mi = 0; mi < 4; mi++) {
        int row0 = rowBase + warp_m * 64 + mi * 16 + r;
        #pragma unroll
        for (int ni = 0; ni < 8; ni++) {
            int col = colBase + warp_n * 64 + ni * 8 + 2 * c;
            float b0 = bias[col], b1 = bias[col + 1];
            float v0 = acc[mi][ni][0] + b0;
            float v1 = acc[mi][ni][1] + b1;
            float v2 = acc[mi][ni][2] + b0;
            float v3 = acc[mi][ni][3] + b1;
            if (EPI == 1) {
                const float2 r0 = *(const float2*)&res[(size_t)row0 * N + col];
                const float2 r1 = *(const float2*)&res[(size_t)(row0 + 8) * N + col];
                v0 += r0.x; v1 += r0.y; v2 += r1.x; v3 += r1.y;
            }
            if (EPI == 2) {
                v0 = gelu_exact(v0); v1 = gelu_exact(v1);
                v2 = gelu_exact(v2); v3 = gelu_exact(v3);
            }
            if (OTF) {
                *(uint2*)&Cu[(size_t)row0 * N + col] =
                    make_uint2(f2tf(v0), f2tf(v1));
                *(uint2*)&Cu[(size_t)(row0 + 8) * N + col] =
                    make_uint2(f2tf(v2), f2tf(v3));
            } else {
                *(float2*)&Cf[(size_t)row0 * N + col]       = make_float2(v0, v1);
                *(float2*)&Cf[(size_t)(row0 + 8) * N + col] = make_float2(v2, v3);
            }
        }
    }
}

// =====================================================================
// TF32 tensor-core flash attention (causal), cp.async 2-stage pipeline
//   Natural layouts: Q[128][68], K[64][68] (bank 4r+c), V[64][72] (8c+r)
//   K/V double-buffered, prefetch distance 1; qkv already tf32 bits
// =====================================================================
#define QST 68            // Q/K smem row stride (64 + 4): bank = 4r+c, bijective
#define VST 72            // V smem row stride (64 + 8): bank = 8c+r, bijective
#define SQP 136           // P staging stride (unchanged)
#define OFF_K 8704        // Qs = 128*68 words
#define OFF_V (8704 + 2 * 64 * QST)
#define OFF_P (OFF_V + 2 * 64 * VST)
#define ATTN_SMEM ((OFF_P + 64 * SQP) * 4)   // 141312 bytes

__global__ void __launch_bounds__(256) attn_tc(const uint32_t* __restrict__ qkv,
                                               uint32_t* __restrict__ out)
{
    extern __shared__ uint32_t asm_[];
    uint32_t sb = smem_u32(asm_);
    uint32_t* Qs = asm_;
    uint32_t* Ps = asm_ + OFF_P;

    int bh = blockIdx.y;
    int b = bh >> 4, h = bh & 15;
    int q0 = blockIdx.x * 128;
    int tid = threadIdx.x;
    int lane = tid & 31, wid = tid >> 5;
    int r = lane >> 2, c = lane & 3;
    int mrow = wid * 16 + r;

    const size_t rowstride = 3 * Dn;
    const uint32_t* base = qkv + (size_t)b * Sn * rowstride + (size_t)h * HDn;
    const uint32_t* baseK = base + Dn;
    const uint32_t* baseV = base + 2 * Dn;

    // loader addressing: K/V tiles 64 rows x 64 words, 4 threads/row
    int krow = tid & 63, kc4 = tid >> 6;     // kc4: 0..3

    // ---- prologue: Q + K/V tile 0 in one cp.async group ----
    {
        int qrow = tid & 127, qc2 = tid >> 7;     // qc2: 0..1
        const uint32_t* qp = base + (size_t)(q0 + qrow) * rowstride + qc2 * 32;
        uint32_t qdst = sb + (uint32_t)((qrow * QST + qc2 * 32) * 4);
        #pragma unroll
        for (int j = 0; j < 8; j++)
            cp_async16(qdst + j * 16, qp + j * 4);

        const uint32_t* kp = baseK + (size_t)krow * rowstride + kc4 * 4;
        const uint32_t* vp = baseV + (size_t)krow * rowstride + kc4 * 4;
        uint32_t kdst = sb + (uint32_t)((OFF_K + krow * QST + kc4 * 4) * 4);
        uint32_t vdst = sb + (uint32_t)((OFF_V + krow * VST + kc4 * 4) * 4);
        #pragma unroll
        for (int j = 0; j < 4; j++) {
            cp_async16(kdst + j * 64, kp + j * 16);   // +16 words gmem, +16 words smem
            cp_async16(vdst + j * 64, vp + j * 16);
        }
        CP_COMMIT();
    }

    float o[8][4];
    #pragma unroll
    for (int ni = 0; ni < 8; ni++)
        #pragma unroll
        for (int e = 0; e < 4; e++) o[ni][e] = 0.f;
    float m0 = -1e30f, m1 = -1e30f, l0 = 0.f, l1 = 0.f;

    int ntiles = 2 * blockIdx.x + 2;
    for (int jt = 0; jt < ntiles; jt++) {
        int kvbuf = jt & 1;
        // prefetch next K/V tile into the other buffer
        if (jt + 1 < ntiles) {
            int nb = kvbuf ^ 1;
            int j0n = (jt + 1) * 64;
            const uint32_t* kp = baseK + (size_t)(j0n + krow) * rowstride + kc4 * 4;
            const uint32_t* vp = baseV + (size_t)(j0n + krow) * rowstride + kc4 * 4;
            uint32_t kdst = sb + (uint32_t)((OFF_K + nb * 64 * QST + krow * QST + kc4 * 4) * 4);
            uint32_t vdst = sb + (uint32_t)((OFF_V + nb * 64 * VST + krow * VST + kc4 * 4) * 4);
            #pragma unroll
            for (int j = 0; j < 4; j++) {
                cp_async16(kdst + j * 64, kp + j * 16);
                cp_async16(vdst + j * 64, vp + j * 16);
            }
            CP_COMMIT();
            CP_WAIT1();   // current tile (and Q) complete; prefetch may fly
        } else {
            CP_WAIT0();
        }
        __syncthreads();  // all threads' copies visible; gates buffer reuse

        const uint32_t* Kc = asm_ + OFF_K + kvbuf * 64 * QST;
        const uint32_t* Vc = asm_ + OFF_V + kvbuf * 64 * VST;
        int j0 = jt * 64;

        // S = Q K^T  (warp tile 16 x 64)
        float s[8][4];
        #pragma unroll
        for (int ni = 0; ni < 8; ni++)
            #pragma unroll
            for (int e = 0; e < 4; e++) s[ni][e] = 0.f;
        #pragma unroll
        for (int k8 = 0; k8 < 8; k8++) {
            int kk = k8 * 8;
            uint32_t af[4];
            af[0] = Qs[mrow * QST + kk + c];
            af[1] = Qs[(mrow + 8) * QST + kk + c];
            af[2] = Qs[mrow * QST + kk + c + 4];
            af[3] = Qs[(mrow + 8) * QST + kk + c + 4];
            #pragma unroll
            for (int ni = 0; ni < 8; ni++) {
                uint32_t b0 = Kc[(ni * 8 + r) * QST + kk + c];
                uint32_t b1 = Kc[(ni * 8 + r) * QST + kk + c + 4];
                mma_tf32(s[ni], af, b0, b1);
            }
        }

        // scale + causal mask
        bool diag = (jt >= 2 * (int)blockIdx.x);
        int qr0 = q0 + mrow, qr1 = q0 + mrow + 8;
        #pragma unroll
        for (int ni = 0; ni < 8; ni++) {
            int col = j0 + ni * 8 + 2 * c;
            float v0 = s[ni][0] * 0.125f;
            float v1 = s[ni][1] * 0.125f;
            float v2 = s[ni][2] * 0.125f;
            float v3 = s[ni][3] * 0.125f;
            if (diag) {
                if (col     > qr0) v0 = -1e30f;
                if (col + 1 > qr0) v1 = -1e30f;
                if (col     > qr1) v2 = -1e30f;
                if (col + 1 > qr1) v3 = -1e30f;
            }
            s[ni][0] = v0; s[ni][1] = v1; s[ni][2] = v2; s[ni][3] = v3;
        }

        // online softmax
        float mx0 = -1e30f, mx1 = -1e30f;
        #pragma unroll
        for (int ni = 0; ni < 8; ni++) {
            mx0 = fmaxf(mx0, fmaxf(s[ni][0], s[ni][1]));
            mx1 = fmaxf(mx1, fmaxf(s[ni][2], s[ni][3]));
        }
        #pragma unroll
        for (int off = 1; off <= 2; off <<= 1) {
            mx0 = fmaxf(mx0, __shfl_xor_sync(0xffffffffu, mx0, off));
            mx1 = fmaxf(mx1, __shfl_xor_sync(0xffffffffu, mx1, off));
        }
        float mn0 = fmaxf(m0, mx0), mn1 = fmaxf(m1, mx1);
        float al0 = __expf(m0 - mn0), al1 = __expf(m1 - mn1);
        m0 = mn0; m1 = mn1;
        float sum0 = 0.f, sum1 = 0.f;
        #pragma unroll
        for (int ni = 0; ni < 8; ni++) {
            s[ni][0] = __expf(s[ni][0] - mn0); sum0 += s[ni][0];
            s[ni][1] = __expf(s[ni][1] - mn0); sum0 += s[ni][1];
            s[ni][2] = __expf(s[ni][2] - mn1); sum1 += s[ni][2];
            s[ni][3] = __expf(s[ni][3] - mn1); sum1 += s[ni][3];
        }
        #pragma unroll
        for (int off = 1; off <= 2; off <<= 1) {
            sum0 += __shfl_xor_sync(0xffffffffu, sum0, off);
            sum1 += __shfl_xor_sync(0xffffffffu, sum1, off);
        }
        l0 = l0 * al0 + sum0;
        l1 = l1 * al1 + sum1;
        #pragma unroll
        for (int ni = 0; ni < 8; ni++) {
            o[ni][0] *= al0; o[ni][1] *= al0;
            o[ni][2] *= al1; o[ni][3] *= al1;
        }

        // stage P (tf32) to per-warp-private smem rows
        #pragma unroll
        for (int ni = 0; ni < 8; ni++) {
            int col = ni * 8 + 2 * c;
            Ps[(col    ) * SQP + mrow    ] = f2tf(s[ni][0]);
            Ps[(col + 1) * SQP + mrow    ] = f2tf(s[ni][1]);
            Ps[(col    ) * SQP + mrow + 8] = f2tf(s[ni][2]);
            Ps[(col + 1) * SQP + mrow + 8] = f2tf(s[ni][3]);
        }
        __syncwarp();

        // O += P @ V
        #pragma unroll
        for (int k8 = 0; k8 < 8; k8++) {
            int kk = k8 * 8;
            uint32_t af[4];
            af[0] = Ps[(kk + c) * SQP + mrow];
            af[1] = Ps[(kk + c) * SQP + mrow + 8];
            af[2] = Ps[(kk + c + 4) * SQP + mrow];
            af[3] = Ps[(kk + c + 4) * SQP + mrow + 8];
            #pragma unroll
            for (int ni = 0; ni < 8; ni++) {
                uint32_t b0 = Vc[(kk + c) * VST + ni * 8 + r];
                uint32_t b1 = Vc[(kk + c + 4) * VST + ni * 8 + r];
                mma_tf32(o[ni], af, b0, b1);
            }
        }
        __syncthreads();  // all warps done with this K/V buffer before reuse
    }

    float il0 = 1.f / l0, il1 = 1.f / l1;
    int row0 = q0 + mrow;
    #pragma unroll
    for (int ni = 0; ni < 8; ni++) {
        int col = h * HDn + ni * 8 + 2 * c;
        *(uint2*)&out[((size_t)b * Sn + row0) * Dn + col] =
            make_uint2(f2tf(o[ni][0] * il0), f2tf(o[ni][1] * il0));
        *(uint2*)&out[((size_t)b * Sn + row0 + 8) * Dn + col] =
            make_uint2(f2tf(o[ni][2] * il1), f2tf(o[ni][3] * il1));
    }
}

// ---------------- launch ----------------
extern "C" void kernel_launch(void* const* d_in, const int* in_sizes, int n_in,
                              void* d_out, int out_size)
{
    const float* x     = (const float*)d_in[0];
    const float* ln1_g = (const float*)d_in[2];
    const float* ln1_b = (const float*)d_in[3];
    const float* w_qkv = (const float*)d_in[4];
    const float* b_qkv = (const float*)d_in[5];
    const float* w_ao  = (const float*)d_in[6];
    const float* b_ao  = (const float*)d_in[7];
    const float* ln2_g = (const float*)d_in[8];
    const float* ln2_b = (const float*)d_in[9];
    const float* w_fc  = (const float*)d_in[10];
    const float* b_fc  = (const float*)d_in[11];
    const float* w_out = (const float*)d_in[12];
    const float* b_out = (const float*)d_in[13];
    float* out = (float*)d_out;

    uint32_t *p_ln1, *p_qkv, *p_att, *p_ln2, *p_fc, *p_wt;
    float *p_x1;
    cudaGetSymbolAddress((void**)&p_ln1, g_ln1);
    cudaGetSymbolAddress((void**)&p_qkv, g_qkv);
    cudaGetSymbolAddress((void**)&p_att, g_att);
    cudaGetSymbolAddress((void**)&p_x1,  g_x1);
    cudaGetSymbolAddress((void**)&p_ln2, g_ln2);
    cudaGetSymbolAddress((void**)&p_fc,  g_fc);
    cudaGetSymbolAddress((void**)&p_wt,  g_wt);

    cudaFuncSetAttribute(attn_tc, cudaFuncAttributeMaxDynamicSharedMemorySize, ATTN_SMEM);
    cudaFuncSetAttribute(gemm_tf32<0,1>, cudaFuncAttributeMaxDynamicSharedMemorySize, GEMM_SMEM);
    cudaFuncSetAttribute(gemm_tf32<1,0>, cudaFuncAttributeMaxDynamicSharedMemorySize, GEMM_SMEM);
    cudaFuncSetAttribute(gemm_tf32<2,1>, cudaFuncAttributeMaxDynamicSharedMemorySize, GEMM_SMEM);

    // 0) weight prep: elementwise tf32 conversion (kept [K,N])
    wconv<<<(1024 * 3072) / 1024, 256>>>(w_qkv, p_wt + WT_QKV);
    wconv<<<(1024 * 1024) / 1024, 256>>>(w_ao,  p_wt + WT_AO);
    wconv<<<(1024 * 4096) / 1024, 256>>>(w_fc,  p_wt + WT_FC);
    wconv<<<(4096 * 1024) / 1024, 256>>>(w_out, p_wt + WT_OUT);

    // 1) LN1 -> tf32
    ln_kernel<<<Mn, 256>>>(x, ln1_g, ln1_b, p_ln1);
    // 2) QKV = LN1 @ w_qkv + b_qkv -> tf32  [8192 x 3072]
    gemm_tf32<0,1><<<dim3(3072 / 256, Mn / 128), 256, GEMM_SMEM>>>(
        p_ln1, p_wt + WT_QKV, b_qkv, nullptr, p_qkv, Mn, 3 * Dn, Dn);
    // 3) causal flash attention (tensor cores, cp.async pipelined) -> tf32
    attn_tc<<<dim3(Sn / 128, Bn * Hn), 256, ATTN_SMEM>>>(p_qkv, p_att);
    // 4) x1 = x + att @ w_ao + b_ao -> fp32
    gemm_tf32<1,0><<<dim3(1024 / 256, Mn / 128), 256, GEMM_SMEM>>>(
        p_att, p_wt + WT_AO, b_ao, x, p_x1, Mn, Dn, Dn);
    // 5) LN2 -> tf32
    ln_kernel<<<Mn, 256>>>(p_x1, ln2_g, ln2_b, p_ln2);
    // 6) fc = gelu(LN2 @ w_fc + b_fc) -> tf32  [8192 x 4096]
    gemm_tf32<2,1><<<dim3(4096 / 256, Mn / 128), 256, GEMM_SMEM>>>(
        p_ln2, p_wt + WT_FC, b_fc, nullptr, p_fc, Mn, 4 * Dn, Dn);
    // 7) out = x1 + fc @ w_out + b_out -> fp32
    gemm_tf32<1,0><<<dim3(1024 / 256, Mn / 128), 256, GEMM_SMEM>>>(
        p_fc, p_wt + WT_OUT, b_out, p_x1, out, Mn, Dn, 4 * Dn);
}

// round 16
// speedup vs baseline: 1.0974x; 1.0974x over previous
#include <cuda_runtime.h>
#include <stdint.h>
#include <math.h>

#define Bn 4
#define Sn 2048
#define Dn 1024
#define Hn 16
#define HDn 64
#define Mn 8192          // B*S

// ---- scratch (allocation-free rule: __device__ globals) ----
__device__ uint32_t g_ln1[(size_t)Mn * Dn];      // tf32 bits
__device__ uint32_t g_qkv[(size_t)Mn * 3 * Dn];  // tf32 bits
__device__ uint32_t g_att[(size_t)Mn * Dn];      // tf32 bits
__device__ float    g_x1 [(size_t)Mn * Dn];      // fp32 (residual + LN2 input)
__device__ uint32_t g_ln2[(size_t)Mn * Dn];      // tf32 bits
__device__ uint32_t g_fc [(size_t)Mn * 4 * Dn];  // tf32 bits
__device__ uint32_t g_wt[12582912];              // 48 MB: tf32 weights [K,N]
#define WT_QKV 0
#define WT_AO  3145728
#define WT_FC  4194304
#define WT_OUT 8388608

// ---------------- helpers ----------------
__device__ __forceinline__ float gelu_exact(float v) {
    return 0.5f * v * (1.0f + erff(v * 0.7071067811865476f));
}
__device__ __forceinline__ uint32_t f2tf(float f) {
    uint32_t u;
    asm("cvt.rna.tf32.f32 %0, %1;" : "=r"(u) : "f"(f));
    return u;
}
__device__ __forceinline__ void mma_tf32(float* d, const uint32_t* a,
                                         uint32_t b0, uint32_t b1) {
    asm volatile(
        "mma.sync.aligned.m16n8k8.row.col.f32.tf32.tf32.f32 "
        "{%0,%1,%2,%3}, {%4,%5,%6,%7}, {%8,%9}, {%0,%1,%2,%3};\n"
        : "+f"(d[0]), "+f"(d[1]), "+f"(d[2]), "+f"(d[3])
        : "r"(a[0]), "r"(a[1]), "r"(a[2]), "r"(a[3]), "r"(b0), "r"(b1));
}
__device__ __forceinline__ uint32_t smem_u32(const void* p) {
    uint32_t a;
    asm("{ .reg .u64 t; cvta.to.shared.u64 t, %1; cvt.u32.u64 %0, t; }"
        : "=r"(a) : "l"(p));
    return a;
}
__device__ __forceinline__ void cp_async16(uint32_t dst, const void* src) {
    asm volatile("cp.async.ca.shared.global [%0], [%1], 16;"
                 :: "r"(dst), "l"(src) : "memory");
}
#define CP_COMMIT() asm volatile("cp.async.commit_group;" ::: "memory")
#define CP_WAIT0()  asm volatile("cp.async.wait_group 0;" ::: "memory")
#define CP_WAIT1()  asm volatile("cp.async.wait_group 1;" ::: "memory")

// ---------------- LayerNorm: fp32 in -> tf32 bits out ----------------
__global__ void __launch_bounds__(256) ln_kernel(const float* __restrict__ x,
                                                 const float* __restrict__ g,
                                                 const float* __restrict__ bta,
                                                 uint32_t* __restrict__ out)
{
    int row = blockIdx.x;
    const float* xr = x + (size_t)row * Dn;
    uint32_t* orow = out + (size_t)row * Dn;
    float s = 0.f, s2 = 0.f;
    for (int i = threadIdx.x; i < Dn; i += 256) {
        float v = xr[i];
        s += v;
        s2 = fmaf(v, v, s2);
    }
    #pragma unroll
    for (int off = 16; off; off >>= 1) {
        s  += __shfl_xor_sync(0xffffffffu, s,  off);
        s2 += __shfl_xor_sync(0xffffffffu, s2, off);
    }
    __shared__ float rs[8], rs2[8];
    int w = threadIdx.x >> 5, lane = threadIdx.x & 31;
    if (lane == 0) { rs[w] = s; rs2[w] = s2; }
    __syncthreads();
    if (threadIdx.x < 32) {
        s  = (lane < 8) ? rs[lane]  : 0.f;
        s2 = (lane < 8) ? rs2[lane] : 0.f;
        #pragma unroll
        for (int off = 4; off; off >>= 1) {
            s  += __shfl_xor_sync(0xffffffffu, s,  off);
            s2 += __shfl_xor_sync(0xffffffffu, s2, off);
        }
        if (lane == 0) { rs[0] = s; rs2[0] = s2; }
    }
    __syncthreads();
    float mu  = rs[0] * (1.f / Dn);
    float var = rs2[0] * (1.f / Dn) - mu * mu;
    float inv = rsqrtf(var + 1e-5f);
    for (int i = threadIdx.x; i < Dn; i += 256) {
        orow[i] = f2tf((xr[i] - mu) * inv * g[i] + bta[i]);
    }
}

// ---------------- weight prep: elementwise fp32 -> tf32 bits ----------------
__global__ void __launch_bounds__(256) wconv(const float* __restrict__ W,
                                             uint32_t* __restrict__ Wt)
{
    int i = (blockIdx.x * 256 + threadIdx.x) * 4;
    float4 v = *(const float4*)(W + i);
    uint4 u;
    u.x = f2tf(v.x); u.y = f2tf(v.y); u.z = f2tf(v.z); u.w = f2tf(v.w);
    *(uint4*)(Wt + i) = u;
}

// =====================================================================
// TF32 tensor-core GEMM, 3-stage cp.async pipeline (A and B both async):
//   CTA tile 128x256, BK=16, 256 threads (8 warps, 2x4 of 64x64)
//   A natural [row][k] stride 20 (banks 20r+c bijective); B [k][n] stride 264
//   one __syncthreads + one commit/wait per k-iter
// EPI: 0 = +bias, 1 = +bias +residual, 2 = +bias then exact GELU
// OTF: 1 = emit tf32 bits, 0 = emit fp32
// =====================================================================
#define AST 20            // A smem row stride (16 + 4)
#define SPB 264           // B smem row stride (256 + 8)
#define ASZW (128 * AST)  // 2560 words per A stage
#define BSZW (16 * SPB)   // 4224 words per B stage
#define BOFFW (3 * ASZW)  // B stages start
#define GEMM_SMEM ((3 * ASZW + 3 * BSZW) * 4)   // 81408 bytes

template<int EPI, int OTF>
__global__ void __launch_bounds__(256) gemm_tf32(
    const uint32_t* __restrict__ A, const uint32_t* __restrict__ Bt,
    const float* __restrict__ bias, const float* __restrict__ res,
    void* __restrict__ Cv, int M, int N, int K)
{
    extern __shared__ uint32_t smem[];
    uint32_t sb = smem_u32(smem);

    int tid = threadIdx.x;
    int lane = tid & 31, wid = tid >> 5;
    int warp_m = wid >> 2;            // 0..1
    int warp_n = wid & 3;             // 0..3
    int r = lane >> 2, c = lane & 3;

    int rowBase = blockIdx.y * 128;
    int colBase = blockIdx.x * 256;

    // A loader: thread -> row tid>>1, k-half (tid&1)*8 words (two 16B ops)
    int arow = tid >> 1;
    int akh  = (tid & 1) * 8;
    const uint32_t* Ap = A + (size_t)(rowBase + arow) * K + akh;
    uint32_t adst0 = sb + (uint32_t)((arow * AST + akh) * 4);

    // B loader: thread -> rows bk0+4j (j=0..3), cols bn4*4 (one 16B op each)
    int bk0 = tid >> 6;               // 0..3
    int bn4 = tid & 63;               // 0..63
    const uint32_t* Bp = Bt + (size_t)bk0 * N + colBase + bn4 * 4;
    uint32_t bdst0 = sb + (uint32_t)((BOFFW + (bk0 * SPB + bn4 * 4)) * 4);

    float acc[4][8][4];
    #pragma unroll
    for (int mi = 0; mi < 4; mi++)
        #pragma unroll
        for (int ni = 0; ni < 8; ni++)
            #pragma unroll
            for (int e = 0; e < 4; e++) acc[mi][ni][e] = 0.f;

    int nk = K >> 4;   // >= 64 always here

    // ---- prologue: issue tiles 0 and 1 as separate groups ----
    {
        cp_async16(adst0,      Ap);
        cp_async16(adst0 + 16, Ap + 4);
        #pragma unroll
        for (int j = 0; j < 4; j++)
            cp_async16(bdst0 + (uint32_t)(j * 4 * SPB * 4), Bp + (size_t)(4 * j) * N);
        CP_COMMIT();
        uint32_t adst1 = adst0 + ASZW * 4;
        uint32_t bdst1 = bdst0 + BSZW * 4;
        cp_async16(adst1,      Ap + 16);
        cp_async16(adst1 + 16, Ap + 20);
        #pragma unroll
        for (int j = 0; j < 4; j++)
            cp_async16(bdst1 + (uint32_t)(j * 4 * SPB * 4),
                       Bp + (size_t)16 * N + (size_t)(4 * j) * N);
        CP_COMMIT();
    }

    int s = 0;  // stage of tile kb
    for (int kb = 0; kb < nk; kb++) {
        CP_WAIT1();        // tile kb complete (one group committed per iter)
        __syncthreads();   // visibility + closes WAR on stage (kb+2)%3

        // issue tile kb+2 into stage (kb+2)%3 (empty group if out of range)
        if (kb + 2 < nk) {
            int ns = (s + 2 >= 3) ? s - 1 : s + 2;
            uint32_t adst = adst0 + (uint32_t)(ns * ASZW * 4);
            uint32_t bdst = bdst0 + (uint32_t)(ns * BSZW * 4);
            const uint32_t* Asrc = Ap + (kb + 2) * 16;
            const uint32_t* Bsrc = Bp + (size_t)((kb + 2) * 16) * N;
            cp_async16(adst,      Asrc);
            cp_async16(adst + 16, Asrc + 4);
            #pragma unroll
            for (int j = 0; j < 4; j++)
                cp_async16(bdst + (uint32_t)(j * 4 * SPB * 4),
                           Bsrc + (size_t)(4 * j) * N);
        }
        CP_COMMIT();

        const uint32_t* Ab = smem + s * ASZW;
        const uint32_t* Bb = smem + BOFFW + s * BSZW;
        #pragma unroll
        for (int ks = 0; ks < 2; ks++) {
            int kk = ks * 8;
            uint32_t af[4][4];
            #pragma unroll
            for (int mi = 0; mi < 4; mi++) {
                int m0 = warp_m * 64 + mi * 16 + r;
                af[mi][0] = Ab[m0 * AST + kk + c];
                af[mi][1] = Ab[(m0 + 8) * AST + kk + c];
                af[mi][2] = Ab[m0 * AST + kk + c + 4];
                af[mi][3] = Ab[(m0 + 8) * AST + kk + c + 4];
            }
            uint32_t bf[8][2];
            #pragma unroll
            for (int ni = 0; ni < 8; ni++) {
                int n0 = warp_n * 64 + ni * 8 + r;
                bf[ni][0] = Bb[(kk + c) * SPB + n0];
                bf[ni][1] = Bb[(kk + c + 4) * SPB + n0];
            }
            #pragma unroll
            for (int mi = 0; mi < 4; mi++)
                #pragma unroll
                for (int ni = 0; ni < 8; ni++)
                    mma_tf32(acc[mi][ni], af[mi], bf[ni][0], bf[ni][1]);
        }
        s = (s + 1 >= 3) ? 0 : s + 1;
    }

    // epilogue: c0,c1 at (r, 2c..2c+1); c2,c3 at (r+8, 2c..2c+1)
    float*    Cf = (float*)Cv;
    uint32_t* Cu = (uint32_t*)Cv;
    #pragma unroll
    for (int mi = 0; mi < 4; mi++) {
        int row0 = rowBase + warp_m * 64 + mi * 16 + r;
        #pragma unroll
        for (int ni = 0; ni < 8; ni++) {
            int col = colBase + warp_n * 64 + ni * 8 + 2 * c;
            float b0 = bias[col], b1 = bias[col + 1];
            float v0 = acc[mi][ni][0] + b0;
            float v1 = acc[mi][ni][1] + b1;
            float v2 = acc[mi][ni][2] + b0;
            float v3 = acc[mi][ni][3] + b1;
            if (EPI == 1) {
                const float2 r0 = *(const float2*)&res[(size_t)row0 * N + col];
                const float2 r1 = *(const float2*)&res[(size_t)(row0 + 8) * N + col];
                v0 += r0.x; v1 += r0.y; v2 += r1.x; v3 += r1.y;
            }
            if (EPI == 2) {
                v0 = gelu_exact(v0); v1 = gelu_exact(v1);
                v2 = gelu_exact(v2); v3 = gelu_exact(v3);
            }
            if (OTF) {
                *(uint2*)&Cu[(size_t)row0 * N + col] =
                    make_uint2(f2tf(v0), f2tf(v1));
                *(uint2*)&Cu[(size_t)(row0 + 8) * N + col] =
                    make_uint2(f2tf(v2), f2tf(v3));
            } else {
                *(float2*)&Cf[(size_t)row0 * N + col]       = make_float2(v0, v1);
                *(float2*)&Cf[(size_t)(row0 + 8) * N + col] = make_float2(v2, v3);
            }
        }
    }
}

// =====================================================================
// TF32 tensor-core flash attention (causal) — R14 version (2 CTAs/SM)
// =====================================================================
#define SQP 136
#define SKP 72
#define ATTN_SMEM ((64 * SQP * 2 + 64 * SKP * 2) * 4)

__global__ void __launch_bounds__(256) attn_tc(const uint32_t* __restrict__ qkv,
                                               uint32_t* __restrict__ out)
{
    extern __shared__ uint32_t asm_[];
    uint32_t* Qs = asm_;
    uint32_t* Ks = Qs + 64 * SQP;
    uint32_t* Vs = Ks + 64 * SKP;
    uint32_t* Ps = Vs + 64 * SKP;

    int bh = blockIdx.y;
    int b = bh >> 4, h = bh & 15;
    int q0 = blockIdx.x * 128;
    int tid = threadIdx.x;
    int lane = tid & 31, wid = tid >> 5;
    int r = lane >> 2, c = lane & 3;
    int mrow = wid * 16 + r;

    const size_t rowstride = 3 * Dn;
    const uint32_t* base = qkv + (size_t)b * Sn * rowstride + (size_t)h * HDn;

    {
        int row = tid & 127, cg = tid >> 7;
        const uint32_t* p = base + (size_t)(q0 + row) * rowstride + cg * 32;
        #pragma unroll
        for (int j = 0; j < 8; j++) {
            uint4 v = *(const uint4*)(p + j * 4);
            int col = cg * 32 + j * 4;
            Qs[(col + 0) * SQP + row] = v.x;
            Qs[(col + 1) * SQP + row] = v.y;
            Qs[(col + 2) * SQP + row] = v.z;
            Qs[(col + 3) * SQP + row] = v.w;
        }
    }

    float o[8][4];
    #pragma unroll
    for (int ni = 0; ni < 8; ni++)
        #pragma unroll
        for (int e = 0; e < 4; e++) o[ni][e] = 0.f;
    float m0 = -1e30f, m1 = -1e30f, l0 = 0.f, l1 = 0.f;

    int ntiles = 2 * blockIdx.x + 2;
    for (int jt = 0; jt < ntiles; jt++) {
        int j0 = jt * 64;
        __syncthreads();
        {
            int row = tid & 63, cg = tid >> 6;
            const uint32_t* pk = base + Dn + (size_t)(j0 + row) * rowstride + cg * 16;
            #pragma unroll
            for (int j = 0; j < 4; j++) {
                uint4 v = *(const uint4*)(pk + j * 4);
                int col = cg * 16 + j * 4;
                Ks[(col + 0) * SKP + row] = v.x;
                Ks[(col + 1) * SKP + row] = v.y;
                Ks[(col + 2) * SKP + row] = v.z;
                Ks[(col + 3) * SKP + row] = v.w;
            }
            int vrow = tid >> 2, vc = (tid & 3) * 16;
            const uint32_t* pv = base + 2 * Dn + (size_t)(j0 + vrow) * rowstride + vc;
            #pragma unroll
            for (int j = 0; j < 4; j++) {
                uint4 v = *(const uint4*)(pv + j * 4);
                uint32_t* d = &Vs[vrow * SKP + vc + j * 4];
                d[0] = v.x; d[1] = v.y; d[2] = v.z; d[3] = v.w;
            }
        }
        __syncthreads();

        float s[8][4];
        #pragma unroll
        for (int ni = 0; ni < 8; ni++)
            #pragma unroll
            for (int e = 0; e < 4; e++) s[ni][e] = 0.f;
        #pragma unroll
        for (int k8 = 0; k8 < 8; k8++) {
            int kk = k8 * 8;
            uint32_t af[4];
            af[0] = Qs[(kk + c) * SQP + mrow];
            af[1] = Qs[(kk + c) * SQP + mrow + 8];
            af[2] = Qs[(kk + c + 4) * SQP + mrow];
            af[3] = Qs[(kk + c + 4) * SQP + mrow + 8];
            #pragma unroll
            for (int ni = 0; ni < 8; ni++) {
                uint32_t b0 = Ks[(kk + c) * SKP + ni * 8 + r];
                uint32_t b1 = Ks[(kk + c + 4) * SKP + ni * 8 + r];
                mma_tf32(s[ni], af, b0, b1);
            }
        }

        bool diag = (jt >= 2 * (int)blockIdx.x);
        int qr0 = q0 + mrow, qr1 = q0 + mrow + 8;
        #pragma unroll
        for (int ni = 0; ni < 8; ni++) {
            int col = j0 + ni * 8 + 2 * c;
            float v0 = s[ni][0] * 0.125f;
            float v1 = s[ni][1] * 0.125f;
            float v2 = s[ni][2] * 0.125f;
            float v3 = s[ni][3] * 0.125f;
            if (diag) {
                if (col     > qr0) v0 = -1e30f;
                if (col + 1 > qr0) v1 = -1e30f;
                if (col     > qr1) v2 = -1e30f;
                if (col + 1 > qr1) v3 = -1e30f;
            }
            s[ni][0] = v0; s[ni][1] = v1; s[ni][2] = v2; s[ni][3] = v3;
        }

        float mx0 = -1e30f, mx1 = -1e30f;
        #pragma unroll
        for (int ni = 0; ni < 8; ni++) {
            mx0 = fmaxf(mx0, fmaxf(s[ni][0], s[ni][1]));
            mx1 = fmaxf(mx1, fmaxf(s[ni][2], s[ni][3]));
        }
        #pragma unroll
        for (int off = 1; off <= 2; off <<= 1) {
            mx0 = fmaxf(mx0, __shfl_xor_sync(0xffffffffu, mx0, off));
            mx1 = fmaxf(mx1, __shfl_xor_sync(0xffffffffu, mx1, off));
        }
        float mn0 = fmaxf(m0, mx0), mn1 = fmaxf(m1, mx1);
        float al0 = __expf(m0 - mn0), al1 = __expf(m1 - mn1);
        m0 = mn0; m1 = mn1;
        float sum0 = 0.f, sum1 = 0.f;
        #pragma unroll
        for (int ni = 0; ni < 8; ni++) {
            s[ni][0] = __expf(s[ni][0] - mn0); sum0 += s[ni][0];
            s[ni][1] = __expf(s[ni][1] - mn0); sum0 += s[ni][1];
            s[ni][2] = __expf(s[ni][2] - mn1); sum1 += s[ni][2];
            s[ni][3] = __expf(s[ni][3] - mn1); sum1 += s[ni][3];
        }
        #pragma unroll
        for (int off = 1; off <= 2; off <<= 1) {
            sum0 += __shfl_xor_sync(0xffffffffu, sum0, off);
            sum1 += __shfl_xor_sync(0xffffffffu, sum1, off);
        }
        l0 = l0 * al0 + sum0;
        l1 = l1 * al1 + sum1;
        #pragma unroll
        for (int ni = 0; ni < 8; ni++) {
            o[ni][0] *= al0; o[ni][1] *= al0;
            o[ni][2] *= al1; o[ni][3] *= al1;
        }

        #pragma unroll
        for (int ni = 0; ni < 8; ni++) {
            int col = ni * 8 + 2 * c;
            Ps[(col    ) * SQP + mrow    ] = f2tf(s[ni][0]);
            Ps[(col + 1) * SQP + mrow    ] = f2tf(s[ni][1]);
            Ps[(col    ) * SQP + mrow + 8] = f2tf(s[ni][2]);
            Ps[(col + 1) * SQP + mrow + 8] = f2tf(s[ni][3]);
        }
        __syncwarp();

        #pragma unroll
        for (int k8 = 0; k8 < 8; k8++) {
            int kk = k8 * 8;
            uint32_t af[4];
            af[0] = Ps[(kk + c) * SQP + mrow];
            af[1] = Ps[(kk + c) * SQP + mrow + 8];
            af[2] = Ps[(kk + c + 4) * SQP + mrow];
            af[3] = Ps[(kk + c + 4) * SQP + mrow + 8];
            #pragma unroll
            for (int ni = 0; ni < 8; ni++) {
                uint32_t b0 = Vs[(kk + c) * SKP + ni * 8 + r];
                uint32_t b1 = Vs[(kk + c + 4) * SKP + ni * 8 + r];
                mma_tf32(o[ni], af, b0, b1);
            }
        }
        __syncwarp();
    }

    float il0 = 1.f / l0, il1 = 1.f / l1;
    int row0 = q0 + mrow;
    #pragma unroll
    for (int ni = 0; ni < 8; ni++) {
        int col = h * HDn + ni * 8 + 2 * c;
        *(uint2*)&out[((size_t)b * Sn + row0) * Dn + col] =
            make_uint2(f2tf(o[ni][0] * il0), f2tf(o[ni][1] * il0));
        *(uint2*)&out[((size_t)b * Sn + row0 + 8) * Dn + col] =
            make_uint2(f2tf(o[ni][2] * il1), f2tf(o[ni][3] * il1));
    }
}

// ---------------- launch ----------------
extern "C" void kernel_launch(void* const* d_in, const int* in_sizes, int n_in,
                              void* d_out, int out_size)
{
    const float* x     = (const float*)d_in[0];
    const float* ln1_g = (const float*)d_in[2];
    const float* ln1_b = (const float*)d_in[3];
    const float* w_qkv = (const float*)d_in[4];
    const float* b_qkv = (const float*)d_in[5];
    const float* w_ao  = (const float*)d_in[6];
    const float* b_ao  = (const float*)d_in[7];
    const float* ln2_g = (const float*)d_in[8];
    const float* ln2_b = (const float*)d_in[9];
    const float* w_fc  = (const float*)d_in[10];
    const float* b_fc  = (const float*)d_in[11];
    const float* w_out = (const float*)d_in[12];
    const float* b_out = (const float*)d_in[13];
    float* out = (float*)d_out;

    uint32_t *p_ln1, *p_qkv, *p_att, *p_ln2, *p_fc, *p_wt;
    float *p_x1;
    cudaGetSymbolAddress((void**)&p_ln1, g_ln1);
    cudaGetSymbolAddress((void**)&p_qkv, g_qkv);
    cudaGetSymbolAddress((void**)&p_att, g_att);
    cudaGetSymbolAddress((void**)&p_x1,  g_x1);
    cudaGetSymbolAddress((void**)&p_ln2, g_ln2);
    cudaGetSymbolAddress((void**)&p_fc,  g_fc);
    cudaGetSymbolAddress((void**)&p_wt,  g_wt);

    cudaFuncSetAttribute(attn_tc, cudaFuncAttributeMaxDynamicSharedMemorySize, ATTN_SMEM);
    cudaFuncSetAttribute(gemm_tf32<0,1>, cudaFuncAttributeMaxDynamicSharedMemorySize, GEMM_SMEM);
    cudaFuncSetAttribute(gemm_tf32<1,0>, cudaFuncAttributeMaxDynamicSharedMemorySize, GEMM_SMEM);
    cudaFuncSetAttribute(gemm_tf32<2,1>, cudaFuncAttributeMaxDynamicSharedMemorySize, GEMM_SMEM);

    // 0) weight prep: elementwise tf32 conversion (kept [K,N])
    wconv<<<(1024 * 3072) / 1024, 256>>>(w_qkv, p_wt + WT_QKV);
    wconv<<<(1024 * 1024) / 1024, 256>>>(w_ao,  p_wt + WT_AO);
    wconv<<<(1024 * 4096) / 1024, 256>>>(w_fc,  p_wt + WT_FC);
    wconv<<<(4096 * 1024) / 1024, 256>>>(w_out, p_wt + WT_OUT);

    // 1) LN1 -> tf32
    ln_kernel<<<Mn, 256>>>(x, ln1_g, ln1_b, p_ln1);
    // 2) QKV = LN1 @ w_qkv + b_qkv -> tf32  [8192 x 3072]
    gemm_tf32<0,1><<<dim3(3072 / 256, Mn / 128), 256, GEMM_SMEM>>>(
        p_ln1, p_wt + WT_QKV, b_qkv, nullptr, p_qkv, Mn, 3 * Dn, Dn);
    // 3) causal flash attention (tensor cores) -> tf32
    attn_tc<<<dim3(Sn / 128, Bn * Hn), 256, ATTN_SMEM>>>(p_qkv, p_att);
    // 4) x1 = x + att @ w_ao + b_ao -> fp32
    gemm_tf32<1,0><<<dim3(1024 / 256, Mn / 128), 256, GEMM_SMEM>>>(
        p_att, p_wt + WT_AO, b_ao, x, p_x1, Mn, Dn, Dn);
    // 5) LN2 -> tf32
    ln_kernel<<<Mn, 256>>>(p_x1, ln2_g, ln2_b, p_ln2);
    // 6) fc = gelu(LN2 @ w_fc + b_fc) -> tf32  [8192 x 4096]
    gemm_tf32<2,1><<<dim3(4096 / 256, Mn / 128), 256, GEMM_SMEM>>>(
        p_ln2, p_wt + WT_FC, b_fc, nullptr, p_fc, Mn, 4 * Dn, Dn);
    // 7) out = x1 + fc @ w_out + b_out -> fp32
    gemm_tf32<1,0><<<dim3(1024 / 256, Mn / 128), 256, GEMM_SMEM>>>(
        p_fc, p_wt + WT_OUT, b_out, p_x1, out, Mn, Dn, 4 * Dn);
}